// round 3
// baseline (speedup 1.0000x reference)
#include <cuda_runtime.h>
#include <math.h>

// Problem dims (fixed by setup_inputs)
#define BB 8
#define QQ 2048
#define SS 2048
#define DD 512
#define EE 512

#define BM 128
#define BN 128
#define BK 8
#define TM 8
#define TN 8

// ---------------------------------------------------------------------------
// NN SGEMM: C[m,n] = sum_k A[m,k] * B[k,n], row-major, batched via blockIdx.z.
// Dims must be multiples of tile sizes (true for all our shapes).
// ---------------------------------------------------------------------------
__global__ __launch_bounds__(256, 2)
void sgemm_nn(const float* __restrict__ A, const float* __restrict__ Bm,
              float* __restrict__ C, int M, int N, int K,
              long sA, long sB, long sC)
{
    __shared__ float As[BK][BM];
    __shared__ float Bs[BK][BN];
    const int bz = blockIdx.z;
    A  += (long)bz * sA;
    Bm += (long)bz * sB;
    C  += (long)bz * sC;
    const int bm = blockIdx.y * BM;
    const int bn = blockIdx.x * BN;
    const int tid = threadIdx.x;
    // A tile: 128 rows x 8 k  -> 256 float4 loads, transpose into As[k][m]
    const int arow = tid >> 1;
    const int acol = (tid & 1) * 4;
    // B tile: 8 k x 128 cols -> 256 float4 loads, direct into Bs[k][n]
    const int brow = tid >> 5;
    const int bcol = (tid & 31) * 4;
    const int tx = (tid & 15) * TN;
    const int ty = (tid >> 4) * TM;

    const float* Aptr = A  + (long)(bm + arow) * K + acol;
    const float* Bptr = Bm + (long)brow * N + (bn + bcol);

    float acc[TM][TN] = {};
    float4 ar = *(const float4*)(Aptr);
    float4 br = *(const float4*)(Bptr);

    for (int k0 = 0; k0 < K; k0 += BK) {
        As[acol + 0][arow] = ar.x;
        As[acol + 1][arow] = ar.y;
        As[acol + 2][arow] = ar.z;
        As[acol + 3][arow] = ar.w;
        *(float4*)&Bs[brow][bcol] = br;
        __syncthreads();
        if (k0 + BK < K) {
            ar = *(const float4*)(Aptr + k0 + BK);
            br = *(const float4*)(Bptr + (long)(k0 + BK) * N);
        }
        #pragma unroll
        for (int k = 0; k < BK; ++k) {
            float af[TM], bf[TN];
            *(float4*)&af[0] = *(const float4*)&As[k][ty];
            *(float4*)&af[4] = *(const float4*)&As[k][ty + 4];
            *(float4*)&bf[0] = *(const float4*)&Bs[k][tx];
            *(float4*)&bf[4] = *(const float4*)&Bs[k][tx + 4];
            #pragma unroll
            for (int i = 0; i < TM; ++i)
                #pragma unroll
                for (int j = 0; j < TN; ++j)
                    acc[i][j] = fmaf(af[i], bf[j], acc[i][j]);
        }
        __syncthreads();
    }

    #pragma unroll
    for (int i = 0; i < TM; ++i) {
        float* cp = C + (long)(bm + ty + i) * N + (bn + tx);
        *(float4*)(cp)     = make_float4(acc[i][0], acc[i][1], acc[i][2], acc[i][3]);
        *(float4*)(cp + 4) = make_float4(acc[i][4], acc[i][5], acc[i][6], acc[i][7]);
    }
}

// ---------------------------------------------------------------------------
// NT SGEMM with mask epilogue: C[m,n] = sum_k A[m,k] * B[n,k];
// columns with mask[n]==0 forced to -inf. Batched via blockIdx.z.
// ---------------------------------------------------------------------------
__global__ __launch_bounds__(256, 2)
void sgemm_nt_mask(const float* __restrict__ A, const float* __restrict__ Bv,
                   const int* __restrict__ mask,
                   float* __restrict__ C, int M, int N, int K,
                   long sA, long sB, long sC)
{
    __shared__ float As[BK][BM];
    __shared__ float Bs[BK][BN];
    const int bz = blockIdx.z;
    A    += (long)bz * sA;
    Bv   += (long)bz * sB;
    C    += (long)bz * sC;
    mask += (long)bz * N;   // mask is [B, S], N == S here
    const int bm = blockIdx.y * BM;
    const int bn = blockIdx.x * BN;
    const int tid = threadIdx.x;
    const int arow = tid >> 1;
    const int acol = (tid & 1) * 4;
    const int tx = (tid & 15) * TN;
    const int ty = (tid >> 4) * TM;

    const float* Aptr = A  + (long)(bm + arow) * K + acol;
    const float* Bptr = Bv + (long)(bn + arow) * K + acol;

    float acc[TM][TN] = {};
    float4 ar = *(const float4*)(Aptr);
    float4 br = *(const float4*)(Bptr);

    for (int k0 = 0; k0 < K; k0 += BK) {
        As[acol + 0][arow] = ar.x;
        As[acol + 1][arow] = ar.y;
        As[acol + 2][arow] = ar.z;
        As[acol + 3][arow] = ar.w;
        Bs[acol + 0][arow] = br.x;
        Bs[acol + 1][arow] = br.y;
        Bs[acol + 2][arow] = br.z;
        Bs[acol + 3][arow] = br.w;
        __syncthreads();
        if (k0 + BK < K) {
            ar = *(const float4*)(Aptr + k0 + BK);
            br = *(const float4*)(Bptr + k0 + BK);
        }
        #pragma unroll
        for (int k = 0; k < BK; ++k) {
            float af[TM], bf[TN];
            *(float4*)&af[0] = *(const float4*)&As[k][ty];
            *(float4*)&af[4] = *(const float4*)&As[k][ty + 4];
            *(float4*)&bf[0] = *(const float4*)&Bs[k][tx];
            *(float4*)&bf[4] = *(const float4*)&Bs[k][tx + 4];
            #pragma unroll
            for (int i = 0; i < TM; ++i)
                #pragma unroll
                for (int j = 0; j < TN; ++j)
                    acc[i][j] = fmaf(af[i], bf[j], acc[i][j]);
        }
        __syncthreads();
    }

    float keep[TN];
    #pragma unroll
    for (int j = 0; j < TN; ++j)
        keep[j] = (mask[bn + tx + j] != 0) ? 1.0f : 0.0f;

    #pragma unroll
    for (int i = 0; i < TM; ++i) {
        float out[TN];
        #pragma unroll
        for (int j = 0; j < TN; ++j)
            out[j] = (keep[j] != 0.0f) ? acc[i][j] : -INFINITY;
        float* cp = C + (long)(bm + ty + i) * N + (bn + tx);
        *(float4*)(cp)     = make_float4(out[0], out[1], out[2], out[3]);
        *(float4*)(cp + 4) = make_float4(out[4], out[5], out[6], out[7]);
    }
}

// ---------------------------------------------------------------------------
// In-place row softmax over S=2048 columns. One block (256 threads) per row.
// ---------------------------------------------------------------------------
__global__ __launch_bounds__(256)
void softmax_rows(float* __restrict__ attn)
{
    __shared__ float sm[32];
    const long row = blockIdx.x;
    float4* p = (float4*)(attn + row * (long)SS);
    const int t = threadIdx.x;
    const int lane = t & 31;
    const int wid = t >> 5;

    float4 v0 = p[t];
    float4 v1 = p[t + 256];

    float m = fmaxf(fmaxf(fmaxf(v0.x, v0.y), fmaxf(v0.z, v0.w)),
                    fmaxf(fmaxf(v1.x, v1.y), fmaxf(v1.z, v1.w)));
    #pragma unroll
    for (int o = 16; o; o >>= 1)
        m = fmaxf(m, __shfl_xor_sync(0xffffffffu, m, o));
    if (lane == 0) sm[wid] = m;
    __syncthreads();
    if (t == 0) {
        float x = sm[0];
        #pragma unroll
        for (int i = 1; i < 8; ++i) x = fmaxf(x, sm[i]);
        sm[8] = x;
    }
    __syncthreads();
    const float rm = sm[8];

    v0.x = expf(v0.x - rm); v0.y = expf(v0.y - rm);
    v0.z = expf(v0.z - rm); v0.w = expf(v0.w - rm);
    v1.x = expf(v1.x - rm); v1.y = expf(v1.y - rm);
    v1.z = expf(v1.z - rm); v1.w = expf(v1.w - rm);

    float s = (v0.x + v0.y + v0.z + v0.w) + (v1.x + v1.y + v1.z + v1.w);
    #pragma unroll
    for (int o = 16; o; o >>= 1)
        s += __shfl_xor_sync(0xffffffffu, s, o);
    if (lane == 0) sm[16 + wid] = s;
    __syncthreads();
    if (t == 0) {
        float x = 0.0f;
        #pragma unroll
        for (int i = 0; i < 8; ++i) x += sm[16 + i];
        sm[24] = x;
    }
    __syncthreads();
    const float inv = 1.0f / sm[24];

    v0.x *= inv; v0.y *= inv; v0.z *= inv; v0.w *= inv;
    v1.x *= inv; v1.y *= inv; v1.z *= inv; v1.w *= inv;
    p[t] = v0;
    p[t + 256] = v1;
}

// ---------------------------------------------------------------------------
// Launch — pure kernel launches, nothing else. No device globals, no scratch:
// tq [B,Q,E] is staged in the context region of d_out (same shape), which is
// only overwritten by the final GEMM, after tq is dead.
// ---------------------------------------------------------------------------
extern "C" void kernel_launch(void* const* d_in, const int* in_sizes, int n_in,
                              void* d_out, int out_size)
{
    const float* query  = (const float*)d_in[0];   // [B, Q, D]
    const float* values = (const float*)d_in[1];   // [B, S, E]
    const int*   mask   = (const int*)d_in[2];     // [B, S]
    const float* W      = (const float*)d_in[3];   // [D, E]

    float* context = (float*)d_out;                          // [B, Q, E]
    float* attn    = (float*)d_out + (size_t)BB * QQ * EE;   // [B, Q, S]
    float* tq      = context;  // scratch alias: dead before G3 writes context

    // G1: tq = query @ W   (M = B*Q, N = E, K = D) -> context region (scratch)
    sgemm_nn<<<dim3(EE / BN, (BB * QQ) / BM, 1), 256>>>(
        query, W, tq, BB * QQ, EE, DD, 0L, 0L, 0L);

    // G2: scores = tq @ values^T per batch, mask to -inf -> attn region
    sgemm_nt_mask<<<dim3(SS / BN, QQ / BM, BB), 256>>>(
        tq, values, mask, attn, QQ, SS, EE,
        (long)QQ * EE, (long)SS * EE, (long)QQ * SS);

    // softmax in place over rows of attn
    softmax_rows<<<BB * QQ, 256>>>(attn);

    // G3: context = attn @ values per batch (overwrites dead tq scratch)
    sgemm_nn<<<dim3(EE / BN, QQ / BM, BB), 256>>>(
        attn, values, context, QQ, EE, SS,
        (long)QQ * SS, (long)SS * EE, (long)QQ * EE);
}

// round 7
// speedup vs baseline: 1.7456x; 1.7456x over previous
#include <cuda_runtime.h>
#include <cuda_bf16.h>
#include <math.h>
#include <stdint.h>

#define BB 8
#define QQ 2048
#define SS 2048
#define DD 512
#define EE 512

#define BKC 32                 // k per chunk
#define ROWB 80                // bytes per smem row: 32 bf16 + 8 pad
#define TILEB (128 * ROWB)     // 10240 per operand tile
#define OFF_AH 0
#define OFF_AL (TILEB)
#define OFF_BH (2 * TILEB)
#define OFF_BL (3 * TILEB)
#define STAGEB (4 * TILEB)     // 40960
#define STAGING_OFF (2 * STAGEB)   // 81920, fp32 [32][132]
#define STAGING_LD 132
#define SMEM_NT (2 * STAGEB)                      // 81920
#define SMEM_TN (STAGING_OFF + 32 * STAGING_LD * 4)  // 98816

__device__ __forceinline__ uint32_t s2u(const void* p) {
    uint32_t a;
    asm("{ .reg .u64 t; cvta.to.shared.u64 t, %1; cvt.u32.u64 %0, t; }" : "=r"(a) : "l"(p));
    return a;
}
__device__ __forceinline__ void cvtpair(float x, float y, uint32_t& h, uint32_t& l) {
    __nv_bfloat16 bx = __float2bfloat16(x), by = __float2bfloat16(y);
    h = (uint32_t)__bfloat16_as_ushort(bx) | ((uint32_t)__bfloat16_as_ushort(by) << 16);
    float rx = x - __bfloat162float(bx), ry = y - __bfloat162float(by);
    asm("cvt.rn.bf16x2.f32 %0, %1, %2;" : "=r"(l) : "f"(ry), "f"(rx));  // lo half = rx
}
#define STS128U(addr, a, b, c, d) \
    asm volatile("st.shared.v4.b32 [%0], {%1, %2, %3, %4};" :: "r"(addr), "r"(a), "r"(b), "r"(c), "r"(d) : "memory")
#define LDSM4(r, addr) \
    asm volatile("ldmatrix.sync.aligned.m8n8.x4.shared.b16 {%0,%1,%2,%3}, [%4];" \
        : "=r"((r)[0]), "=r"((r)[1]), "=r"((r)[2]), "=r"((r)[3]) : "r"(addr))
#define LDSM2(r, addr) \
    asm volatile("ldmatrix.sync.aligned.m8n8.x2.shared.b16 {%0,%1}, [%2];" \
        : "=r"((r)[0]), "=r"((r)[1]) : "r"(addr))
#define MMA16816(d, a, b) \
    asm volatile("mma.sync.aligned.m16n8k16.row.col.f32.bf16.bf16.f32 " \
        "{%0,%1,%2,%3}, {%4,%5,%6,%7}, {%8,%9}, {%0,%1,%2,%3};" \
        : "+f"((d)[0]), "+f"((d)[1]), "+f"((d)[2]), "+f"((d)[3]) \
        : "r"((a)[0]), "r"((a)[1]), "r"((a)[2]), "r"((a)[3]), "r"((b)[0]), "r"((b)[1]))

__device__ __forceinline__ void ldg4(float4* r, const float* p) {
    const float4* q = (const float4*)p;
    r[0] = __ldg(q); r[1] = __ldg(q + 1); r[2] = __ldg(q + 2); r[3] = __ldg(q + 3);
}
// 16 floats -> 8 hi bf16x2 + 8 lo bf16x2, two STS128 each
__device__ __forceinline__ void cvt_sts16(const float4* r, uint32_t ha, uint32_t la) {
    uint32_t h[8], l[8];
    cvtpair(r[0].x, r[0].y, h[0], l[0]); cvtpair(r[0].z, r[0].w, h[1], l[1]);
    cvtpair(r[1].x, r[1].y, h[2], l[2]); cvtpair(r[1].z, r[1].w, h[3], l[3]);
    cvtpair(r[2].x, r[2].y, h[4], l[4]); cvtpair(r[2].z, r[2].w, h[5], l[5]);
    cvtpair(r[3].x, r[3].y, h[6], l[6]); cvtpair(r[3].z, r[3].w, h[7], l[7]);
    STS128U(ha, h[0], h[1], h[2], h[3]); STS128U(ha + 16, h[4], h[5], h[6], h[7]);
    STS128U(la, l[0], l[1], l[2], l[3]); STS128U(la + 16, l[4], l[5], l[6], l[7]);
}

// C[128x128] = A[M,K](k-major) x B. TRANSB=0: B [N,K] k-major. TRANSB=1: B [K,N] row-major.
template <bool TRANSB, bool MASK>
__global__ __launch_bounds__(256, 1)
void mma_gemm(const float* __restrict__ Ag, const float* __restrict__ Bg,
              const int* __restrict__ maskg, float* __restrict__ Cg,
              int K, int lda, int ldb, int ldc, long sA, long sB, long sC)
{
    extern __shared__ char smem[];
    const uint32_t sb = s2u(smem);
    const int tid = threadIdx.x, w = tid >> 5, lane = tid & 31;
    const int bz = blockIdx.z;
    const float* A = Ag + (long)bz * sA;
    const float* B = Bg + (long)bz * sB;
    float* C = Cg + (long)bz * sC;
    const int bm = blockIdx.y * 128, bn = blockIdx.x * 128;
    const int m0 = (w & 1) * 64, n0 = (w >> 1) * 32;   // warp tile 64x32

    const int arow = tid >> 1, ahalf = tid & 1;        // A/B(NT)/trans-write mapping
    const int tkr = tid >> 3, tnq = tid & 7;           // TRANSB staging mapping

    float d[4][4][4] = {};
    float4 aR[4], bR[4];

    // ---- prologue: chunk 0 into stage 0 ----
    ldg4(aR, A + (long)(bm + arow) * lda + ahalf * 16);
    if (!TRANSB) ldg4(bR, B + (long)(bn + arow) * ldb + ahalf * 16);
    else         ldg4(bR, B + (long)tkr * ldb + bn + tnq * 16);
    cvt_sts16(aR, sb + OFF_AH + arow * ROWB + ahalf * 32,
                  sb + OFF_AL + arow * ROWB + ahalf * 32);
    if (!TRANSB) {
        cvt_sts16(bR, sb + OFF_BH + arow * ROWB + ahalf * 32,
                      sb + OFF_BL + arow * ROWB + ahalf * 32);
    } else {
        uint32_t st = sb + STAGING_OFF + (uint32_t)((tkr * STAGING_LD + tnq * 16) * 4);
        #pragma unroll
        for (int i = 0; i < 4; ++i)
            asm volatile("st.shared.v4.f32 [%0], {%1,%2,%3,%4};"
                :: "r"(st + i * 16), "f"(bR[i].x), "f"(bR[i].y), "f"(bR[i].z), "f"(bR[i].w) : "memory");
        __syncthreads();
        float4 tv[4];
        #pragma unroll
        for (int i = 0; i < 16; ++i) {
            uint32_t ad = sb + STAGING_OFF + (uint32_t)((((ahalf * 16 + i) * STAGING_LD) + arow) * 4);
            asm volatile("ld.shared.f32 %0, [%1];" : "=f"(((float*)tv)[i]) : "r"(ad));
        }
        cvt_sts16(tv, sb + OFF_BH + arow * ROWB + ahalf * 32,
                      sb + OFF_BL + arow * ROWB + ahalf * 32);
    }
    __syncthreads();

    const int NC = K / BKC;
    for (int c = 0; c < NC; ++c) {
        const uint32_t stage = sb + (uint32_t)((c & 1) * STAGEB);
        const bool pf = (c + 1 < NC);
        const int kn = (c + 1) * BKC;
        if (pf) {
            ldg4(aR, A + (long)(bm + arow) * lda + kn + ahalf * 16);
            if (!TRANSB) ldg4(bR, B + (long)(bn + arow) * ldb + kn + ahalf * 16);
            else         ldg4(bR, B + (long)(kn + tkr) * ldb + bn + tnq * 16);
        }
        // ---- compute current stage: 2 k-steps of m16n8k16, hi/lo compensated ----
        #pragma unroll
        for (int ks = 0; ks < 2; ++ks) {
            uint32_t ah[4][4], al[4][4], bh[4][2], bl[4][2];
            const uint32_t akoff = ks * 32 + (lane >> 4) * 16;
            const uint32_t bkoff = ks * 32 + ((lane >> 3) & 1) * 16;
            #pragma unroll
            for (int mt = 0; mt < 4; ++mt) {
                uint32_t ro = (uint32_t)((m0 + mt * 16 + (lane & 15)) * ROWB);
                LDSM4(ah[mt], stage + OFF_AH + ro + akoff);
                LDSM4(al[mt], stage + OFF_AL + ro + akoff);
            }
            #pragma unroll
            for (int nt = 0; nt < 4; ++nt) {
                uint32_t ro = (uint32_t)((n0 + nt * 8 + (lane & 7)) * ROWB);
                LDSM2(bh[nt], stage + OFF_BH + ro + bkoff);
                LDSM2(bl[nt], stage + OFF_BL + ro + bkoff);
            }
            #pragma unroll
            for (int mt = 0; mt < 4; ++mt)
                #pragma unroll
                for (int nt = 0; nt < 4; ++nt) {
                    MMA16816(d[mt][nt], ah[mt], bh[nt]);
                    MMA16816(d[mt][nt], ah[mt], bl[nt]);
                    MMA16816(d[mt][nt], al[mt], bh[nt]);
                }
        }
        if (pf) {
            const uint32_t nst = sb + (uint32_t)(((c + 1) & 1) * STAGEB);
            cvt_sts16(aR, nst + OFF_AH + arow * ROWB + ahalf * 32,
                          nst + OFF_AL + arow * ROWB + ahalf * 32);
            if (!TRANSB) {
                cvt_sts16(bR, nst + OFF_BH + arow * ROWB + ahalf * 32,
                              nst + OFF_BL + arow * ROWB + ahalf * 32);
            } else {
                uint32_t st = sb + STAGING_OFF + (uint32_t)((tkr * STAGING_LD + tnq * 16) * 4);
                #pragma unroll
                for (int i = 0; i < 4; ++i)
                    asm volatile("st.shared.v4.f32 [%0], {%1,%2,%3,%4};"
                        :: "r"(st + i * 16), "f"(bR[i].x), "f"(bR[i].y), "f"(bR[i].z), "f"(bR[i].w) : "memory");
                __syncthreads();
                float4 tv[4];
                #pragma unroll
                for (int i = 0; i < 16; ++i) {
                    uint32_t ad = sb + STAGING_OFF + (uint32_t)((((ahalf * 16 + i) * STAGING_LD) + arow) * 4);
                    asm volatile("ld.shared.f32 %0, [%1];" : "=f"(((float*)tv)[i]) : "r"(ad));
                }
                cvt_sts16(tv, nst + OFF_BH + arow * ROWB + ahalf * 32,
                              nst + OFF_BL + arow * ROWB + ahalf * 32);
            }
        }
        __syncthreads();
    }

    // ---- epilogue ----
    const int* mrow = MASK ? (maskg + (long)bz * ldc) : (const int*)0;
    #pragma unroll
    for (int mt = 0; mt < 4; ++mt) {
        #pragma unroll
        for (int nt = 0; nt < 4; ++nt) {
            int r0 = bm + m0 + mt * 16 + (lane >> 2);
            int col = bn + n0 + nt * 8 + (lane & 3) * 2;
            float v0 = d[mt][nt][0], v1 = d[mt][nt][1];
            float v2 = d[mt][nt][2], v3 = d[mt][nt][3];
            if (MASK) {
                int k0 = __ldg(mrow + col), k1 = __ldg(mrow + col + 1);
                if (!k0) { v0 = -INFINITY; v2 = -INFINITY; }
                if (!k1) { v1 = -INFINITY; v3 = -INFINITY; }
            }
            float2* c0 = (float2*)(C + (long)r0 * ldc + col);
            float2* c1 = (float2*)(C + (long)(r0 + 8) * ldc + col);
            *c0 = make_float2(v0, v1);
            *c1 = make_float2(v2, v3);
        }
    }
}

__global__ __launch_bounds__(256)
void softmax_rows(float* __restrict__ attn)
{
    __shared__ float sm[32];
    const long row = blockIdx.x;
    float4* p = (float4*)(attn + row * (long)SS);
    const int t = threadIdx.x, lane = t & 31, wid = t >> 5;
    float4 v0 = p[t], v1 = p[t + 256];
    float m = fmaxf(fmaxf(fmaxf(v0.x, v0.y), fmaxf(v0.z, v0.w)),
                    fmaxf(fmaxf(v1.x, v1.y), fmaxf(v1.z, v1.w)));
    #pragma unroll
    for (int o = 16; o; o >>= 1) m = fmaxf(m, __shfl_xor_sync(0xffffffffu, m, o));
    if (lane == 0) sm[wid] = m;
    __syncthreads();
    if (t == 0) {
        float x = sm[0];
        #pragma unroll
        for (int i = 1; i < 8; ++i) x = fmaxf(x, sm[i]);
        sm[8] = x;
    }
    __syncthreads();
    const float rm = sm[8];
    v0.x = expf(v0.x - rm); v0.y = expf(v0.y - rm);
    v0.z = expf(v0.z - rm); v0.w = expf(v0.w - rm);
    v1.x = expf(v1.x - rm); v1.y = expf(v1.y - rm);
    v1.z = expf(v1.z - rm); v1.w = expf(v1.w - rm);
    float s = (v0.x + v0.y + v0.z + v0.w) + (v1.x + v1.y + v1.z + v1.w);
    #pragma unroll
    for (int o = 16; o; o >>= 1) s += __shfl_xor_sync(0xffffffffu, s, o);
    if (lane == 0) sm[16 + wid] = s;
    __syncthreads();
    if (t == 0) {
        float x = 0.0f;
        #pragma unroll
        for (int i = 0; i < 8; ++i) x += sm[16 + i];
        sm[24] = x;
    }
    __syncthreads();
    const float inv = 1.0f / sm[24];
    v0.x *= inv; v0.y *= inv; v0.z *= inv; v0.w *= inv;
    v1.x *= inv; v1.y *= inv; v1.z *= inv; v1.w *= inv;
    p[t] = v0; p[t + 256] = v1;
}

extern "C" void kernel_launch(void* const* d_in, const int* in_sizes, int n_in,
                              void* d_out, int out_size)
{
    const float* query  = (const float*)d_in[0];
    const float* values = (const float*)d_in[1];
    const int*   mask   = (const int*)d_in[2];
    const float* W      = (const float*)d_in[3];

    float* context = (float*)d_out;
    float* attn    = (float*)d_out + (size_t)BB * QQ * EE;
    float* tq      = context;  // dead before G3 writes context

    cudaFuncSetAttribute(mma_gemm<true,  false>, cudaFuncAttributeMaxDynamicSharedMemorySize, SMEM_TN);
    cudaFuncSetAttribute(mma_gemm<false, true>,  cudaFuncAttributeMaxDynamicSharedMemorySize, SMEM_NT);

    // G1: tq = query @ W  (W is [K,N] row-major -> TRANSB)
    mma_gemm<true, false><<<dim3(EE/128, (BB*QQ)/128, 1), 256, SMEM_TN>>>(
        query, W, (const int*)0, tq, DD, DD, EE, EE, 0L, 0L, 0L);

    // G2: scores = tq @ values^T + mask  (values [S,E] is [n][k] -> NT)
    mma_gemm<false, true><<<dim3(SS/128, QQ/128, BB), 256, SMEM_NT>>>(
        tq, values, mask, attn, EE, EE, EE, SS,
        (long)QQ*EE, (long)SS*EE, (long)QQ*SS);

    softmax_rows<<<BB*QQ, 256>>>(attn);

    // G3: context = attn @ values  (values [K,N] row-major -> TRANSB)
    mma_gemm<true, false><<<dim3(EE/128, QQ/128, BB), 256, SMEM_TN>>>(
        attn, values, (const int*)0, context, SS, SS, EE, EE,
        (long)QQ*SS, (long)SS*EE, (long)QQ*EE);
}

// round 8
// speedup vs baseline: 2.0085x; 1.1506x over previous
#include <cuda_runtime.h>
#include <cuda_bf16.h>
#include <math.h>
#include <stdint.h>

#define BB 8
#define QQ 2048
#define SS 2048
#define DD 512
#define EE 512

#define BKC 32                 // k per chunk
#define ROWB 80                // bytes per smem row: 32 bf16 + 8 pad
#define TILEB (128 * ROWB)     // 10240 per operand tile
#define OFF_AH 0
#define OFF_AL (TILEB)
#define OFF_BH (2 * TILEB)
#define OFF_BL (3 * TILEB)
#define STAGEB (4 * TILEB)     // 40960
#define SMEM_SZ (2 * STAGEB)   // 81920

// Pre-transposed operands (device-global scratch is the sanctioned mechanism)
__device__ float g_wt[(size_t)EE * DD];            // W^T   [E][D]
__device__ float g_vt[(size_t)BB * EE * SS];       // values^T per batch [B][E][S]

__device__ __forceinline__ uint32_t s2u(const void* p) {
    uint32_t a;
    asm("{ .reg .u64 t; cvta.to.shared.u64 t, %1; cvt.u32.u64 %0, t; }" : "=r"(a) : "l"(p));
    return a;
}
__device__ __forceinline__ void cvtpair(float x, float y, uint32_t& h, uint32_t& l) {
    __nv_bfloat16 bx = __float2bfloat16(x), by = __float2bfloat16(y);
    h = (uint32_t)__bfloat16_as_ushort(bx) | ((uint32_t)__bfloat16_as_ushort(by) << 16);
    float rx = x - __bfloat162float(bx), ry = y - __bfloat162float(by);
    asm("cvt.rn.bf16x2.f32 %0, %1, %2;" : "=r"(l) : "f"(ry), "f"(rx));  // lo half = rx
}
#define STS128U(addr, a, b, c, d) \
    asm volatile("st.shared.v4.b32 [%0], {%1, %2, %3, %4};" :: "r"(addr), "r"(a), "r"(b), "r"(c), "r"(d) : "memory")
#define LDSM4(r, addr) \
    asm volatile("ldmatrix.sync.aligned.m8n8.x4.shared.b16 {%0,%1,%2,%3}, [%4];" \
        : "=r"((r)[0]), "=r"((r)[1]), "=r"((r)[2]), "=r"((r)[3]) : "r"(addr))
#define MMA16816(d, a, b) \
    asm volatile("mma.sync.aligned.m16n8k16.row.col.f32.bf16.bf16.f32 " \
        "{%0,%1,%2,%3}, {%4,%5,%6,%7}, {%8,%9}, {%0,%1,%2,%3};" \
        : "+f"((d)[0]), "+f"((d)[1]), "+f"((d)[2]), "+f"((d)[3]) \
        : "r"((a)[0]), "r"((a)[1]), "r"((a)[2]), "r"((a)[3]), "r"((b)[0]), "r"((b)[1]))

__device__ __forceinline__ void ldg4(float4* r, const float* p) {
    const float4* q = (const float4*)p;
    r[0] = __ldg(q); r[1] = __ldg(q + 1); r[2] = __ldg(q + 2); r[3] = __ldg(q + 3);
}
__device__ __forceinline__ void cvt_sts16(const float4* r, uint32_t ha, uint32_t la) {
    uint32_t h[8], l[8];
    cvtpair(r[0].x, r[0].y, h[0], l[0]); cvtpair(r[0].z, r[0].w, h[1], l[1]);
    cvtpair(r[1].x, r[1].y, h[2], l[2]); cvtpair(r[1].z, r[1].w, h[3], l[3]);
    cvtpair(r[2].x, r[2].y, h[4], l[4]); cvtpair(r[2].z, r[2].w, h[5], l[5]);
    cvtpair(r[3].x, r[3].y, h[6], l[6]); cvtpair(r[3].z, r[3].w, h[7], l[7]);
    STS128U(ha, h[0], h[1], h[2], h[3]); STS128U(ha + 16, h[4], h[5], h[6], h[7]);
    STS128U(la, l[0], l[1], l[2], l[3]); STS128U(la + 16, l[4], l[5], l[6], l[7]);
}

// ---------------------------------------------------------------------------
// 32x32 tiled fp32 transpose: dst[C][R] = src[R][C], batched over z.
// DSEL: 1 -> g_wt, 2 -> g_vt
// ---------------------------------------------------------------------------
template <int DSEL>
__global__ __launch_bounds__(256)
void transpose_k(const float* __restrict__ src, int R, int C, long sS, long sD)
{
    __shared__ float t[32][33];
    float* dst = (DSEL == 1) ? g_wt : g_vt;
    src += (long)blockIdx.z * sS;
    dst += (long)blockIdx.z * sD;
    const int r0 = blockIdx.y * 32, c0 = blockIdx.x * 32;
    const int tx = threadIdx.x & 31, ty = threadIdx.x >> 5;  // 32x8
    #pragma unroll
    for (int i = ty; i < 32; i += 8)
        t[i][tx] = src[(long)(r0 + i) * C + c0 + tx];
    __syncthreads();
    #pragma unroll
    for (int i = ty; i < 32; i += 8)
        dst[(long)(c0 + i) * R + r0 + tx] = t[tx][i];
}

// ---------------------------------------------------------------------------
// NT GEMM: C[m][n] = sum_k A[m][k] * Brow[n][k], hi/lo bf16 compensated.
// BSEL: 0 -> Bg arg, 1 -> g_wt, 2 -> g_vt.
// ---------------------------------------------------------------------------
template <int BSEL, bool MASK>
__global__ __launch_bounds__(256, 1)
void mma_gemm(const float* __restrict__ Ag, const float* __restrict__ Bg,
              const int* __restrict__ maskg, float* __restrict__ Cg,
              int K, int lda, int ldb, int ldc, long sA, long sB, long sC)
{
    extern __shared__ char smem[];
    const uint32_t sb = s2u(smem);
    const int tid = threadIdx.x, w = tid >> 5, lane = tid & 31;
    const int bz = blockIdx.z;
    const float* A = Ag + (long)bz * sA;
    const float* B = ((BSEL == 0) ? Bg : (BSEL == 1) ? (const float*)g_wt : (const float*)g_vt)
                     + (long)bz * sB;
    float* C = Cg + (long)bz * sC;
    const int bm = blockIdx.y * 128, bn = blockIdx.x * 128;
    const int m0 = (w & 1) * 64, n0 = (w >> 1) * 32;   // warp tile 64x32

    const int arow = tid >> 1, ahalf = tid & 1;

    float d[4][4][4] = {};
    float4 aR[4], bR[4];

    // prologue: chunk 0 -> stage 0
    ldg4(aR, A + (long)(bm + arow) * lda + ahalf * 16);
    ldg4(bR, B + (long)(bn + arow) * ldb + ahalf * 16);
    cvt_sts16(aR, sb + OFF_AH + arow * ROWB + ahalf * 32,
                  sb + OFF_AL + arow * ROWB + ahalf * 32);
    cvt_sts16(bR, sb + OFF_BH + arow * ROWB + ahalf * 32,
                  sb + OFF_BL + arow * ROWB + ahalf * 32);
    __syncthreads();

    const int NC = K / BKC;
    for (int c = 0; c < NC; ++c) {
        const uint32_t stage = sb + (uint32_t)((c & 1) * STAGEB);
        const bool pf = (c + 1 < NC);
        if (pf) {
            const int kn = (c + 1) * BKC;
            ldg4(aR, A + (long)(bm + arow) * lda + kn + ahalf * 16);
            ldg4(bR, B + (long)(bn + arow) * ldb + kn + ahalf * 16);
        }
        #pragma unroll
        for (int ks = 0; ks < 2; ++ks) {
            uint32_t ah[4][4], al[4][4], bh[4][2], bl[4][2];
            const uint32_t akoff = ks * 32 + (lane >> 4) * 16;
            #pragma unroll
            for (int mt = 0; mt < 4; ++mt) {
                uint32_t ro = (uint32_t)((m0 + mt * 16 + (lane & 15)) * ROWB);
                LDSM4(ah[mt], stage + OFF_AH + ro + akoff);
                LDSM4(al[mt], stage + OFF_AL + ro + akoff);
            }
            const uint32_t bkoff = ks * 32 + ((lane >> 3) & 1) * 16;
            #pragma unroll
            for (int np = 0; np < 2; ++np) {   // x4: two n-tiles per ldmatrix
                uint32_t ro = (uint32_t)((n0 + np * 16 + ((lane >> 4) << 3) + (lane & 7)) * ROWB);
                uint32_t r4[4];
                LDSM4(r4, stage + OFF_BH + ro + bkoff);
                bh[np*2][0] = r4[0]; bh[np*2][1] = r4[1];
                bh[np*2+1][0] = r4[2]; bh[np*2+1][1] = r4[3];
                LDSM4(r4, stage + OFF_BL + ro + bkoff);
                bl[np*2][0] = r4[0]; bl[np*2][1] = r4[1];
                bl[np*2+1][0] = r4[2]; bl[np*2+1][1] = r4[3];
            }
            #pragma unroll
            for (int mt = 0; mt < 4; ++mt)
                #pragma unroll
                for (int nt = 0; nt < 4; ++nt) {
                    MMA16816(d[mt][nt], ah[mt], bh[nt]);
                    MMA16816(d[mt][nt], ah[mt], bl[nt]);
                    MMA16816(d[mt][nt], al[mt], bh[nt]);
                }
        }
        if (pf) {
            const uint32_t nst = sb + (uint32_t)(((c + 1) & 1) * STAGEB);
            cvt_sts16(aR, nst + OFF_AH + arow * ROWB + ahalf * 32,
                          nst + OFF_AL + arow * ROWB + ahalf * 32);
            cvt_sts16(bR, nst + OFF_BH + arow * ROWB + ahalf * 32,
                          nst + OFF_BL + arow * ROWB + ahalf * 32);
        }
        __syncthreads();
    }

    const int* mrow = MASK ? (maskg + (long)bz * ldc) : (const int*)0;
    #pragma unroll
    for (int mt = 0; mt < 4; ++mt) {
        #pragma unroll
        for (int nt = 0; nt < 4; ++nt) {
            int r0 = bm + m0 + mt * 16 + (lane >> 2);
            int col = bn + n0 + nt * 8 + (lane & 3) * 2;
            float v0 = d[mt][nt][0], v1 = d[mt][nt][1];
            float v2 = d[mt][nt][2], v3 = d[mt][nt][3];
            if (MASK) {
                int k0 = __ldg(mrow + col), k1 = __ldg(mrow + col + 1);
                if (!k0) { v0 = -INFINITY; v2 = -INFINITY; }
                if (!k1) { v1 = -INFINITY; v3 = -INFINITY; }
            }
            *(float2*)(C + (long)r0 * ldc + col)       = make_float2(v0, v1);
            *(float2*)(C + (long)(r0 + 8) * ldc + col) = make_float2(v2, v3);
        }
    }
}

__global__ __launch_bounds__(256)
void softmax_rows(float* __restrict__ attn)
{
    __shared__ float sm[32];
    const long row = blockIdx.x;
    float4* p = (float4*)(attn + row * (long)SS);
    const int t = threadIdx.x, lane = t & 31, wid = t >> 5;
    float4 v0 = p[t], v1 = p[t + 256];
    float m = fmaxf(fmaxf(fmaxf(v0.x, v0.y), fmaxf(v0.z, v0.w)),
                    fmaxf(fmaxf(v1.x, v1.y), fmaxf(v1.z, v1.w)));
    #pragma unroll
    for (int o = 16; o; o >>= 1) m = fmaxf(m, __shfl_xor_sync(0xffffffffu, m, o));
    if (lane == 0) sm[wid] = m;
    __syncthreads();
    if (t == 0) {
        float x = sm[0];
        #pragma unroll
        for (int i = 1; i < 8; ++i) x = fmaxf(x, sm[i]);
        sm[8] = x;
    }
    __syncthreads();
    const float rm = sm[8];
    v0.x = expf(v0.x - rm); v0.y = expf(v0.y - rm);
    v0.z = expf(v0.z - rm); v0.w = expf(v0.w - rm);
    v1.x = expf(v1.x - rm); v1.y = expf(v1.y - rm);
    v1.z = expf(v1.z - rm); v1.w = expf(v1.w - rm);
    float s = (v0.x + v0.y + v0.z + v0.w) + (v1.x + v1.y + v1.z + v1.w);
    #pragma unroll
    for (int o = 16; o; o >>= 1) s += __shfl_xor_sync(0xffffffffu, s, o);
    if (lane == 0) sm[16 + wid] = s;
    __syncthreads();
    if (t == 0) {
        float x = 0.0f;
        #pragma unroll
        for (int i = 0; i < 8; ++i) x += sm[16 + i];
        sm[24] = x;
    }
    __syncthreads();
    const float inv = 1.0f / sm[24];
    v0.x *= inv; v0.y *= inv; v0.z *= inv; v0.w *= inv;
    v1.x *= inv; v1.y *= inv; v1.z *= inv; v1.w *= inv;
    p[t] = v0; p[t + 256] = v1;
}

extern "C" void kernel_launch(void* const* d_in, const int* in_sizes, int n_in,
                              void* d_out, int out_size)
{
    const float* query  = (const float*)d_in[0];
    const float* values = (const float*)d_in[1];
    const int*   mask   = (const int*)d_in[2];
    const float* W      = (const float*)d_in[3];

    float* context = (float*)d_out;
    float* attn    = (float*)d_out + (size_t)BB * QQ * EE;
    float* tq      = context;  // dead before G3 writes context

    cudaFuncSetAttribute(mma_gemm<1, false>, cudaFuncAttributeMaxDynamicSharedMemorySize, SMEM_SZ);
    cudaFuncSetAttribute(mma_gemm<0, true>,  cudaFuncAttributeMaxDynamicSharedMemorySize, SMEM_SZ);
    cudaFuncSetAttribute(mma_gemm<2, false>, cudaFuncAttributeMaxDynamicSharedMemorySize, SMEM_SZ);

    // T1: g_wt = W^T  (W [D,E] -> [E,D])
    transpose_k<1><<<dim3(EE/32, DD/32, 1), 256>>>(W, DD, EE, 0L, 0L);
    // T2: g_vt = values^T per batch ([S,E] -> [E,S])
    transpose_k<2><<<dim3(EE/32, SS/32, BB), 256>>>(values, SS, EE,
        (long)SS*EE, (long)EE*SS);

    // G1: tq = query @ W      (B = g_wt [E][D], NT)
    mma_gemm<1, false><<<dim3(EE/128, (BB*QQ)/128, 1), 256, SMEM_SZ>>>(
        query, (const float*)0, (const int*)0, tq, DD, DD, DD, EE, 0L, 0L, 0L);

    // G2: scores = tq @ values^T + mask  (B = values [S][E], natural NT)
    mma_gemm<0, true><<<dim3(SS/128, QQ/128, BB), 256, SMEM_SZ>>>(
        tq, values, mask, attn, EE, EE, EE, SS,
        (long)QQ*EE, (long)SS*EE, (long)QQ*SS);

    softmax_rows<<<BB*QQ, 256>>>(attn);

    // G3: context = attn @ values  (B = g_vt [E][S], NT)
    mma_gemm<2, false><<<dim3(EE/128, QQ/128, BB), 256, SMEM_SZ>>>(
        attn, (const float*)0, (const int*)0, context, SS, SS, SS, EE,
        (long)QQ*SS, (long)EE*SS, (long)QQ*EE);
}